// round 1
// baseline (speedup 1.0000x reference)
#include <cuda_runtime.h>
#include <math.h>
#include <math_constants.h>

// Problem constants
#define T_STEPS 16
#define BATCH   8
#define HH      224
#define WW      224
#define CIN     3
#define CH      32
#define OUT     10
#define NIMG    (T_STEPS * BATCH)      // 128
#define KW      113                     // W/2 + 1
#define MAGN    (HH * KW)               // 25312 per image

// -------- device scratch (no allocation allowed) --------
__device__ float2 d_rowspec[(size_t)NIMG * MAGN];   // [img][k][y], ~26 MB
__device__ float  d_mag    [(size_t)NIMG * MAGN];   // [img][y][k], ~13 MB
__device__ float2 d_tw[WW];                          // exp(-2*pi*i*n/224)
__device__ int    d_counts[T_STEPS * BATCH * CH];    // spike counts per (t,b,c)
__device__ double d_esum;                            // sum of log1p(mag)

// ============================================================
// K0: init twiddles (exact, via double sinpi/cospi), zero accums
// ============================================================
__global__ void k_init() {
    int tid = blockIdx.x * blockDim.x + threadIdx.x;
    if (tid < T_STEPS * BATCH * CH) d_counts[tid] = 0;
    if (tid == 0) d_esum = 0.0;
    if (tid < WW) {
        double a = (double)tid / 112.0;   // 2*n/224
        d_tw[tid] = make_float2((float)cospi(a), (float)(-sinpi(a)));
    }
}

// ============================================================
// K1: gray + row rfft.  One block per (img,y) row. 128 threads.
// X[k] = sum_w gray[w] * exp(-2*pi*i*k*w/224),  k = 0..112
// Write transposed: rowspec[img][k][y] so K2 reads contiguously.
// ============================================================
__global__ void k_rowdft(const float* __restrict__ x_seq) {
    int row = blockIdx.x;             // 0 .. NIMG*HH-1
    int img = row / HH;
    int y   = row % HH;

    __shared__ float  g[WW];
    __shared__ float2 tws[WW];

    int tid = threadIdx.x;
    const float* base = x_seq + (((size_t)img * HH + y) * WW) * CIN;
    for (int w = tid; w < WW; w += 128) {
        const float* p = base + w * 3;
        g[w] = (p[0] + p[1] + p[2]) * (1.0f / 3.0f);
        tws[w] = d_tw[w];
    }
    __syncthreads();

    int k = tid;
    if (k < KW) {
        float ar = 0.0f, ai = 0.0f;
        int idx = 0;
        #pragma unroll 8
        for (int w = 0; w < WW; ++w) {
            float gv = g[w];
            float2 t = tws[idx];
            ar = fmaf(gv, t.x, ar);
            ai = fmaf(gv, t.y, ai);
            idx += k; if (idx >= WW) idx -= WW;
        }
        d_rowspec[(size_t)img * MAGN + (size_t)k * HH + y] = make_float2(ar, ai);
    }
}

// ============================================================
// K2: column full DFT + log1p(|.|) + energy accumulation.
// One block per (img,k) column. 224 threads (7 warps), thread m
// computes output bin m.  Writes mag[img][m][k].
// ============================================================
__global__ void k_coldft() {
    int blk = blockIdx.x;             // img*KW + k
    int img = blk / KW;
    int k   = blk % KW;

    __shared__ float2 Z[HH];
    __shared__ float2 tws[HH];
    __shared__ float  warps[7];

    int tid = threadIdx.x;            // 0..223
    Z[tid]   = d_rowspec[(size_t)img * MAGN + (size_t)k * HH + tid];
    tws[tid] = d_tw[tid];
    __syncthreads();

    int m = tid;
    float ar = 0.0f, ai = 0.0f;
    int idx = 0;
    #pragma unroll 8
    for (int h = 0; h < HH; ++h) {
        float2 z = Z[h];
        float2 t = tws[idx];
        ar = fmaf(z.x, t.x, fmaf(-z.y, t.y, ar));
        ai = fmaf(z.x, t.y, fmaf( z.y, t.x, ai));
        idx += m; if (idx >= WW) idx -= WW;
    }
    float mag = log1pf(sqrtf(fmaf(ar, ar, ai * ai)));
    d_mag[(size_t)img * MAGN + (size_t)m * KW + k] = mag;

    // block sum for spectral energy
    float s = mag;
    #pragma unroll
    for (int o = 16; o; o >>= 1) s += __shfl_down_sync(0xffffffffu, s, o);
    if ((tid & 31) == 0) warps[tid >> 5] = s;
    __syncthreads();
    if (tid == 0) {
        float tot = 0.0f;
        #pragma unroll
        for (int i = 0; i < 7; ++i) tot += warps[i];
        atomicAdd(&d_esum, (double)tot);
    }
}

// ============================================================
// K3: fused 3x3 conv (4->32 ch) + LIF scan over T.
// Grid: (196 tiles of 16x16, BATCH). Block: 256 threads =
//   (c = tid&31 : output channel, g = tid>>5 : row pair 2g,2g+1).
// Each thread keeps its channel's 36 weights + V[2][16] in regs.
// Input tile (4ch, 18x18 halo) staged in smem each timestep;
// channel 3 is the clamp-to-edge lerp upsample of d_mag.
// ============================================================
__global__ void __launch_bounds__(256, 2)
k_convlif(const float* __restrict__ x_seq,
          const float* __restrict__ conv_w,
          const float* __restrict__ conv_b) {
    int b    = blockIdx.y;
    int tile = blockIdx.x;                 // 0..195
    int ty0 = (tile / 14) * 16;
    int tx0 = (tile % 14) * 16;

    int tid = threadIdx.x;
    int c = tid & 31;
    int g = tid >> 5;

    // per-channel weights -> registers
    float wreg[3][3][4];
    #pragma unroll
    for (int ky = 0; ky < 3; ++ky)
        #pragma unroll
        for (int kx = 0; kx < 3; ++kx)
            #pragma unroll
            for (int i = 0; i < 4; ++i)
                wreg[ky][kx][i] = conv_w[(((ky * 3) + kx) * 4 + i) * CH + c];
    float bc = conv_b[c];

    __shared__ float tile_s[4][18][18];
    __shared__ int   cnt_s[CH];

    float V[2][16];
    #pragma unroll
    for (int r = 0; r < 2; ++r)
        #pragma unroll
        for (int x = 0; x < 16; ++x) V[r][x] = 0.0f;

    const float scale = 113.0f / 224.0f;

    for (int t = 0; t < T_STEPS; ++t) {
        int img = t * BATCH + b;
        __syncthreads();                    // prior iter done with tile_s / cnt_s
        if (tid < CH) cnt_s[tid] = 0;

        // ---- stage input tile (with zero SAME padding) ----
        for (int p = tid; p < 18 * 18; p += 256) {
            int yy = p / 18, xx = p % 18;
            int gy = ty0 - 1 + yy, gx = tx0 - 1 + xx;
            float r0 = 0.f, r1 = 0.f, r2 = 0.f, mv = 0.f;
            if (gy >= 0 && gy < HH && gx >= 0 && gx < WW) {
                const float* px = x_seq + ((((size_t)img * HH + gy) * WW) + gx) * CIN;
                r0 = px[0]; r1 = px[1]; r2 = px[2];
                const float* mrow = d_mag + (size_t)img * MAGN + (size_t)gy * KW;
                float src = fmaf((float)gx + 0.5f, scale, -0.5f);
                if (src <= 0.0f)        mv = mrow[0];
                else if (src >= 112.0f) mv = mrow[112];
                else {
                    int i0 = (int)src;
                    float f = src - (float)i0;
                    float a = mrow[i0], bb = mrow[i0 + 1];
                    mv = fmaf(f, bb - a, a);
                }
            }
            tile_s[0][yy][xx] = r0;
            tile_s[1][yy][xx] = r1;
            tile_s[2][yy][xx] = r2;
            tile_s[3][yy][xx] = mv;
        }
        __syncthreads();

        // ---- leak + bias ----
        #pragma unroll
        for (int r = 0; r < 2; ++r)
            #pragma unroll
            for (int x = 0; x < 16; ++x)
                V[r][x] = fmaf(0.9f, V[r][x], bc);

        // ---- conv taps ----
        #pragma unroll
        for (int i = 0; i < 4; ++i) {
            #pragma unroll
            for (int iy = 0; iy < 4; ++iy) {
                int sy = 2 * g + iy;        // smem row for input row (out0-1+iy)
                float v[18];
                #pragma unroll
                for (int x = 0; x < 18; ++x) v[x] = tile_s[i][sy][x];
                if (iy < 3) {               // contributes to out row 0 with ky=iy
                    float w0 = wreg[iy][0][i], w1 = wreg[iy][1][i], w2 = wreg[iy][2][i];
                    #pragma unroll
                    for (int x = 0; x < 16; ++x)
                        V[0][x] = fmaf(w0, v[x], fmaf(w1, v[x + 1], fmaf(w2, v[x + 2], V[0][x])));
                }
                if (iy >= 1) {              // contributes to out row 1 with ky=iy-1
                    float w0 = wreg[iy - 1][0][i], w1 = wreg[iy - 1][1][i], w2 = wreg[iy - 1][2][i];
                    #pragma unroll
                    for (int x = 0; x < 16; ++x)
                        V[1][x] = fmaf(w0, v[x], fmaf(w1, v[x + 1], fmaf(w2, v[x + 2], V[1][x])));
                }
            }
        }

        // ---- spike + soft reset + count ----
        int cnt = 0;
        #pragma unroll
        for (int r = 0; r < 2; ++r)
            #pragma unroll
            for (int x = 0; x < 16; ++x) {
                if (V[r][x] > 1.0f) { V[r][x] -= 1.0f; ++cnt; }
            }
        atomicAdd(&cnt_s[c], cnt);
        __syncthreads();
        if (tid < CH) atomicAdd(&d_counts[(t * BATCH + b) * CH + tid], cnt_s[tid]);
    }
}

// ============================================================
// K4: head matmul + readout + scalars.
// out layout: [0..79] readout (B,OUT); [80..1359] logits (T,B,OUT);
//             [1360] spike rate; [1361] spectral energy.
// ============================================================
__global__ void k_final(const float* __restrict__ head_w,
                        const float* __restrict__ head_b,
                        float* __restrict__ out) {
    __shared__ float logits_s[T_STEPS][BATCH][OUT];
    int tid = threadIdx.x;              // 256

    if (tid < T_STEPS * BATCH) {
        int t = tid >> 3, b = tid & 7;
        const float inv = 1.0f / (float)(HH * WW);
        float mean[CH];
        #pragma unroll
        for (int c = 0; c < CH; ++c)
            mean[c] = (float)d_counts[(t * BATCH + b) * CH + c] * inv;
        #pragma unroll
        for (int o = 0; o < OUT; ++o) {
            float a = head_b[o];
            #pragma unroll
            for (int c = 0; c < CH; ++c)
                a = fmaf(mean[c], head_w[c * OUT + o], a);
            logits_s[t][b][o] = a;
            out[80 + (t * BATCH + b) * OUT + o] = a;
        }
    }
    __syncthreads();
    if (tid < BATCH * OUT) {
        int b = tid / OUT, o = tid % OUT;
        float s = 0.0f;
        #pragma unroll
        for (int t = 0; t < T_STEPS; ++t) s += logits_s[t][b][o];
        out[tid] = s * (1.0f / (float)T_STEPS);
    }
    if (tid == 0) {
        long long tot = 0;
        for (int i = 0; i < T_STEPS * BATCH * CH; ++i) tot += (long long)d_counts[i];
        out[1360] = (float)((double)tot /
                            ((double)T_STEPS * BATCH * HH * WW * CH));
        out[1361] = (float)(d_esum / ((double)T_STEPS * BATCH * HH * KW));
    }
}

// ============================================================
extern "C" void kernel_launch(void* const* d_in, const int* in_sizes, int n_in,
                              void* d_out, int out_size) {
    const float* x_seq  = (const float*)d_in[0];
    const float* conv_w = (const float*)d_in[1];
    const float* conv_b = (const float*)d_in[2];
    const float* head_w = (const float*)d_in[3];
    const float* head_b = (const float*)d_in[4];
    float* out = (float*)d_out;

    k_init<<<16, 256>>>();
    k_rowdft<<<NIMG * HH, 128>>>(x_seq);
    k_coldft<<<NIMG * KW, 224>>>();
    k_convlif<<<dim3(14 * 14, BATCH), 256>>>(x_seq, conv_w, conv_b);
    k_final<<<1, 256>>>(head_w, head_b, out);
}

// round 2
// speedup vs baseline: 2.0370x; 2.0370x over previous
#include <cuda_runtime.h>
#include <math.h>
#include <math_constants.h>

// Problem constants
#define T_STEPS 16
#define BATCH   8
#define HH      224
#define WW      224
#define CIN     3
#define CH      32
#define OUT     10
#define NIMG    (T_STEPS * BATCH)      // 128
#define KW      113                     // W/2 + 1
#define HALF    112
#define NF      111                     // folded pair count (w = 1..111)
#define MAGN    (HH * KW)               // 25312 per image

// -------- device scratch (no allocation allowed) --------
__device__ float2 d_rowspec[(size_t)NIMG * MAGN];   // [img][k][y], ~26 MB
__device__ float  d_mag    [(size_t)NIMG * MAGN];   // [img][y][k], ~13 MB
__device__ float2 d_tw[WW];                          // exp(-2*pi*i*n/224)
__device__ int    d_counts[T_STEPS * BATCH * CH];    // spike counts per (t,b,c)
__device__ double d_esum;                            // sum of log1p(mag)

// ============================================================
// K0: init twiddles (exact, via double sinpi/cospi), zero accums
// ============================================================
__global__ void k_init() {
    int tid = blockIdx.x * blockDim.x + threadIdx.x;
    if (tid < T_STEPS * BATCH * CH) d_counts[tid] = 0;
    if (tid == 0) d_esum = 0.0;
    if (tid < WW) {
        double a = (double)tid / 112.0;   // 2*n/224
        d_tw[tid] = make_float2((float)cospi(a), (float)(-sinpi(a)));
    }
}

// ============================================================
// K1: gray + row rDFT, folded + 16-row register tile.
// Block = (img, group of 16 rows). 128 threads; thread k<113
// computes bin k for all 16 rows.
//   X[k] = g0 + (-1)^k g112 + sum_{w=1}^{111} [ s_w cos - i d_w sin ]
// with s_w = g[w]+g[224-w], d_w = g[w]-g[224-w], tw=(cos,-sin):
//   ar += s*t.x ;  ai += d*t.y
// Output transposed: rowspec[img][k][y] (128B/thread, float4).
// ============================================================
__global__ void __launch_bounds__(128) k_rowdft(const float* __restrict__ x_seq) {
    int blk = blockIdx.x;             // img*14 + yg
    int img = blk / 14;
    int y0  = (blk % 14) * 16;

    __shared__ float  g_s[WW * 17];       // [w][r], stride 17 (anti-conflict)
    __shared__ float  s_s[NF * 16];       // [w-1][r]
    __shared__ float  dd_s[NF * 16];
    __shared__ float2 tw_s[WW];
    __shared__ float  g0_s[16], g112_s[16];

    int tid = threadIdx.x;
    for (int i = tid; i < WW; i += 128) tw_s[i] = d_tw[i];

    // gray: 16 rows x 224 px, coalesced reads
    for (int p = tid; p < 16 * WW; p += 128) {
        int r = p / WW, w = p % WW;
        const float* px = x_seq + ((((size_t)img * HH + (y0 + r)) * WW) + w) * CIN;
        g_s[w * 17 + r] = (px[0] + px[1] + px[2]) * (1.0f / 3.0f);
    }
    __syncthreads();

    // fold
    for (int p = tid; p < NF * 16; p += 128) {
        int w = p >> 4, r = p & 15;          // actual pair index w+1
        float a = g_s[(w + 1) * 17 + r];
        float b = g_s[(223 - w) * 17 + r];   // 224-(w+1)
        s_s[p]  = a + b;
        dd_s[p] = a - b;
    }
    if (tid < 16) { g0_s[tid] = g_s[tid]; g112_s[tid] = g_s[HALF * 17 + tid]; }
    __syncthreads();

    int k = tid;
    if (k >= KW) return;

    float ar[16], ai[16];
    float sgn = (k & 1) ? -1.0f : 1.0f;
    #pragma unroll
    for (int r = 0; r < 16; ++r) {
        ar[r] = g0_s[r] + sgn * g112_s[r];
        ai[r] = 0.0f;
    }

    int idx = k;
    for (int w = 0; w < NF; ++w) {
        float2 t = tw_s[idx];
        const float4* sp = (const float4*)(s_s  + w * 16);
        const float4* dp = (const float4*)(dd_s + w * 16);
        #pragma unroll
        for (int q = 0; q < 4; ++q) {
            float4 sv = sp[q], dv = dp[q];
            ar[q*4+0] = fmaf(sv.x, t.x, ar[q*4+0]);
            ar[q*4+1] = fmaf(sv.y, t.x, ar[q*4+1]);
            ar[q*4+2] = fmaf(sv.z, t.x, ar[q*4+2]);
            ar[q*4+3] = fmaf(sv.w, t.x, ar[q*4+3]);
            ai[q*4+0] = fmaf(dv.x, t.y, ai[q*4+0]);
            ai[q*4+1] = fmaf(dv.y, t.y, ai[q*4+1]);
            ai[q*4+2] = fmaf(dv.z, t.y, ai[q*4+2]);
            ai[q*4+3] = fmaf(dv.w, t.y, ai[q*4+3]);
        }
        idx += k; if (idx >= WW) idx -= WW;
    }

    // 128B contiguous store per thread
    float4* out = (float4*)(d_rowspec + (size_t)img * MAGN + (size_t)k * HH + y0);
    #pragma unroll
    for (int j = 0; j < 8; ++j)
        out[j] = make_float4(ar[2*j], ai[2*j], ar[2*j+1], ai[2*j+1]);
}

// ============================================================
// K2: column full DFT (folded) + log1p(|.|) + energy.
// Block = (img, group of 8 k-columns). 224 threads; thread m
// computes output row m for 8 columns.
//   X[m] = Z0 + (-1)^m Z112 + sum_{h=1}^{111} [Zs*cos - i*Zd*sin]
// with tw=(cos,-sin):
//   ar += Zs.re*t.x - Zd.im*t.y ;  ai += Zs.im*t.x + Zd.re*t.y
// ============================================================
__global__ void __launch_bounds__(224) k_coldft() {
    int blk = blockIdx.x;             // img*15 + kg
    int img = blk / 15;
    int k0  = (blk % 15) * 8;
    int nk  = KW - k0; if (nk > 8) nk = 8;

    __shared__ float2 zraw[8 * 225];      // [kk][h], stride 225
    __shared__ float2 zs_s[NF * 8];       // [w][kk]
    __shared__ float2 zd_s[NF * 8];
    __shared__ float2 z0_s[8], z112_s[8];
    __shared__ float2 tw_s[WW];
    __shared__ float  wsum[7];

    int tid = threadIdx.x;
    for (int i = tid; i < WW; i += 224) tw_s[i] = d_tw[i];

    // load columns (coalesced in h); zero-pad invalid kk
    for (int p = tid; p < 8 * HH; p += 224) {
        int kk = p / HH, h = p % HH;
        float2 z = make_float2(0.0f, 0.0f);
        if (kk < nk)
            z = d_rowspec[(size_t)img * MAGN + (size_t)(k0 + kk) * HH + h];
        zraw[kk * 225 + h] = z;
    }
    __syncthreads();

    // fold
    for (int p = tid; p < NF * 8; p += 224) {
        int kk = p & 7, w = p >> 3;        // actual h = w+1
        float2 a = zraw[kk * 225 + (w + 1)];
        float2 b = zraw[kk * 225 + (223 - w)];
        zs_s[w * 8 + kk] = make_float2(a.x + b.x, a.y + b.y);
        zd_s[w * 8 + kk] = make_float2(a.x - b.x, a.y - b.y);
    }
    if (tid < 8) {
        z0_s[tid]   = zraw[tid * 225];
        z112_s[tid] = zraw[tid * 225 + HALF];
    }
    __syncthreads();

    int m = tid;                           // 0..223
    float ar[8], ai[8];
    float sgn = (m & 1) ? -1.0f : 1.0f;
    #pragma unroll
    for (int kk = 0; kk < 8; ++kk) {
        ar[kk] = z0_s[kk].x + sgn * z112_s[kk].x;
        ai[kk] = z0_s[kk].y + sgn * z112_s[kk].y;
    }

    int idx = m;
    for (int w = 0; w < NF; ++w) {
        float2 t = tw_s[idx];
        const float4* zsp = (const float4*)(zs_s + w * 8);   // 4x float4 = 8 float2
        const float4* zdp = (const float4*)(zd_s + w * 8);
        #pragma unroll
        for (int q = 0; q < 4; ++q) {
            float4 a = zsp[q], b = zdp[q];
            // a = (zs[2q].re, zs[2q].im, zs[2q+1].re, zs[2q+1].im)
            ar[2*q]   = fmaf(a.x, t.x, fmaf(-b.y, t.y, ar[2*q]));
            ai[2*q]   = fmaf(a.y, t.x, fmaf( b.x, t.y, ai[2*q]));
            ar[2*q+1] = fmaf(a.z, t.x, fmaf(-b.w, t.y, ar[2*q+1]));
            ai[2*q+1] = fmaf(a.w, t.x, fmaf( b.z, t.y, ai[2*q+1]));
        }
        idx += m; if (idx >= WW) idx -= WW;
    }

    // magnitude, store, energy
    float esum = 0.0f;
    float* mrow = d_mag + (size_t)img * MAGN + (size_t)m * KW + k0;
    #pragma unroll
    for (int kk = 0; kk < 8; ++kk) {
        if (kk < nk) {
            float mag = log1pf(sqrtf(fmaf(ar[kk], ar[kk], ai[kk] * ai[kk])));
            mrow[kk] = mag;
            esum += mag;
        }
    }
    #pragma unroll
    for (int o = 16; o; o >>= 1) esum += __shfl_down_sync(0xffffffffu, esum, o);
    if ((tid & 31) == 0) wsum[tid >> 5] = esum;
    __syncthreads();
    if (tid == 0) {
        float tot = 0.0f;
        #pragma unroll
        for (int i = 0; i < 7; ++i) tot += wsum[i];
        atomicAdd(&d_esum, (double)tot);
    }
}

// ============================================================
// K3: fused 3x3 conv (4->32 ch) + LIF scan over T. (unchanged)
// ============================================================
__global__ void __launch_bounds__(256, 2)
k_convlif(const float* __restrict__ x_seq,
          const float* __restrict__ conv_w,
          const float* __restrict__ conv_b) {
    int b    = blockIdx.y;
    int tile = blockIdx.x;                 // 0..195
    int ty0 = (tile / 14) * 16;
    int tx0 = (tile % 14) * 16;

    int tid = threadIdx.x;
    int c = tid & 31;
    int g = tid >> 5;

    float wreg[3][3][4];
    #pragma unroll
    for (int ky = 0; ky < 3; ++ky)
        #pragma unroll
        for (int kx = 0; kx < 3; ++kx)
            #pragma unroll
            for (int i = 0; i < 4; ++i)
                wreg[ky][kx][i] = conv_w[(((ky * 3) + kx) * 4 + i) * CH + c];
    float bc = conv_b[c];

    __shared__ float tile_s[4][18][18];
    __shared__ int   cnt_s[CH];

    float V[2][16];
    #pragma unroll
    for (int r = 0; r < 2; ++r)
        #pragma unroll
        for (int x = 0; x < 16; ++x) V[r][x] = 0.0f;

    const float scale = 113.0f / 224.0f;

    for (int t = 0; t < T_STEPS; ++t) {
        int img = t * BATCH + b;
        __syncthreads();
        if (tid < CH) cnt_s[tid] = 0;

        for (int p = tid; p < 18 * 18; p += 256) {
            int yy = p / 18, xx = p % 18;
            int gy = ty0 - 1 + yy, gx = tx0 - 1 + xx;
            float r0 = 0.f, r1 = 0.f, r2 = 0.f, mv = 0.f;
            if (gy >= 0 && gy < HH && gx >= 0 && gx < WW) {
                const float* px = x_seq + ((((size_t)img * HH + gy) * WW) + gx) * CIN;
                r0 = px[0]; r1 = px[1]; r2 = px[2];
                const float* mrow = d_mag + (size_t)img * MAGN + (size_t)gy * KW;
                float src = fmaf((float)gx + 0.5f, scale, -0.5f);
                if (src <= 0.0f)        mv = mrow[0];
                else if (src >= 112.0f) mv = mrow[112];
                else {
                    int i0 = (int)src;
                    float f = src - (float)i0;
                    float a = mrow[i0], bb = mrow[i0 + 1];
                    mv = fmaf(f, bb - a, a);
                }
            }
            tile_s[0][yy][xx] = r0;
            tile_s[1][yy][xx] = r1;
            tile_s[2][yy][xx] = r2;
            tile_s[3][yy][xx] = mv;
        }
        __syncthreads();

        #pragma unroll
        for (int r = 0; r < 2; ++r)
            #pragma unroll
            for (int x = 0; x < 16; ++x)
                V[r][x] = fmaf(0.9f, V[r][x], bc);

        #pragma unroll
        for (int i = 0; i < 4; ++i) {
            #pragma unroll
            for (int iy = 0; iy < 4; ++iy) {
                int sy = 2 * g + iy;
                float v[18];
                #pragma unroll
                for (int x = 0; x < 18; ++x) v[x] = tile_s[i][sy][x];
                if (iy < 3) {
                    float w0 = wreg[iy][0][i], w1 = wreg[iy][1][i], w2 = wreg[iy][2][i];
                    #pragma unroll
                    for (int x = 0; x < 16; ++x)
                        V[0][x] = fmaf(w0, v[x], fmaf(w1, v[x + 1], fmaf(w2, v[x + 2], V[0][x])));
                }
                if (iy >= 1) {
                    float w0 = wreg[iy - 1][0][i], w1 = wreg[iy - 1][1][i], w2 = wreg[iy - 1][2][i];
                    #pragma unroll
                    for (int x = 0; x < 16; ++x)
                        V[1][x] = fmaf(w0, v[x], fmaf(w1, v[x + 1], fmaf(w2, v[x + 2], V[1][x])));
                }
            }
        }

        int cnt = 0;
        #pragma unroll
        for (int r = 0; r < 2; ++r)
            #pragma unroll
            for (int x = 0; x < 16; ++x) {
                if (V[r][x] > 1.0f) { V[r][x] -= 1.0f; ++cnt; }
            }
        atomicAdd(&cnt_s[c], cnt);
        __syncthreads();
        if (tid < CH) atomicAdd(&d_counts[(t * BATCH + b) * CH + tid], cnt_s[tid]);
    }
}

// ============================================================
// K4: head matmul + readout + scalars. (unchanged)
// ============================================================
__global__ void k_final(const float* __restrict__ head_w,
                        const float* __restrict__ head_b,
                        float* __restrict__ out) {
    __shared__ float logits_s[T_STEPS][BATCH][OUT];
    int tid = threadIdx.x;

    if (tid < T_STEPS * BATCH) {
        int t = tid >> 3, b = tid & 7;
        const float inv = 1.0f / (float)(HH * WW);
        float mean[CH];
        #pragma unroll
        for (int c = 0; c < CH; ++c)
            mean[c] = (float)d_counts[(t * BATCH + b) * CH + c] * inv;
        #pragma unroll
        for (int o = 0; o < OUT; ++o) {
            float a = head_b[o];
            #pragma unroll
            for (int c = 0; c < CH; ++c)
                a = fmaf(mean[c], head_w[c * OUT + o], a);
            logits_s[t][b][o] = a;
            out[80 + (t * BATCH + b) * OUT + o] = a;
        }
    }
    __syncthreads();
    if (tid < BATCH * OUT) {
        int b = tid / OUT, o = tid % OUT;
        float s = 0.0f;
        #pragma unroll
        for (int t = 0; t < T_STEPS; ++t) s += logits_s[t][b][o];
        out[tid] = s * (1.0f / (float)T_STEPS);
    }
    if (tid == 0) {
        long long tot = 0;
        for (int i = 0; i < T_STEPS * BATCH * CH; ++i) tot += (long long)d_counts[i];
        out[1360] = (float)((double)tot /
                            ((double)T_STEPS * BATCH * HH * WW * CH));
        out[1361] = (float)(d_esum / ((double)T_STEPS * BATCH * HH * KW));
    }
}

// ============================================================
extern "C" void kernel_launch(void* const* d_in, const int* in_sizes, int n_in,
                              void* d_out, int out_size) {
    const float* x_seq  = (const float*)d_in[0];
    const float* conv_w = (const float*)d_in[1];
    const float* conv_b = (const float*)d_in[2];
    const float* head_w = (const float*)d_in[3];
    const float* head_b = (const float*)d_in[4];
    float* out = (float*)d_out;

    k_init<<<16, 256>>>();
    k_rowdft<<<NIMG * 14, 128>>>(x_seq);
    k_coldft<<<NIMG * 15, 224>>>();
    k_convlif<<<dim3(14 * 14, BATCH), 256>>>(x_seq, conv_w, conv_b);
    k_final<<<1, 256>>>(head_w, head_b, out);
}

// round 3
// speedup vs baseline: 2.4157x; 1.1859x over previous
#include <cuda_runtime.h>
#include <math.h>
#include <math_constants.h>

// Problem constants
#define T_STEPS 16
#define BATCH   8
#define HH      224
#define WW      224
#define CIN     3
#define CH      32
#define OUT     10
#define NIMG    (T_STEPS * BATCH)      // 128
#define KW      113                     // W/2 + 1
#define HALF    112
#define NF      111                     // folded pair count (w = 1..111)
#define MAGN    (HH * KW)               // 25312 per image

// -------- device scratch (no allocation allowed) --------
__device__ float2 d_rowspec[(size_t)NIMG * MAGN];   // [img][k][y], ~26 MB
__device__ float  d_mag    [(size_t)NIMG * MAGN];   // [img][y][k], ~13 MB
__device__ float2 d_tw[WW];                          // exp(-2*pi*i*n/224)
__device__ int    d_counts[T_STEPS * BATCH * CH];    // spike counts per (t,b,c)
__device__ double d_esum;                            // sum of log1p(mag)

// ============================================================
// K0: init twiddles (exact, via double sinpi/cospi), zero accums
// ============================================================
__global__ void k_init() {
    int tid = blockIdx.x * blockDim.x + threadIdx.x;
    if (tid < T_STEPS * BATCH * CH) d_counts[tid] = 0;
    if (tid == 0) d_esum = 0.0;
    if (tid < WW) {
        double a = (double)tid / 112.0;   // 2*n/224
        d_tw[tid] = make_float2((float)cospi(a), (float)(-sinpi(a)));
    }
}

// ============================================================
// K1: gray + row rDFT, folded + 16-row register tile.
// ============================================================
__global__ void __launch_bounds__(128) k_rowdft(const float* __restrict__ x_seq) {
    int blk = blockIdx.x;             // img*14 + yg
    int img = blk / 14;
    int y0  = (blk % 14) * 16;

    __shared__ float  g_s[WW * 17];       // [w][r], stride 17 (anti-conflict)
    __shared__ float  s_s[NF * 16];       // [w-1][r]
    __shared__ float  dd_s[NF * 16];
    __shared__ float2 tw_s[WW];
    __shared__ float  g0_s[16], g112_s[16];

    int tid = threadIdx.x;
    for (int i = tid; i < WW; i += 128) tw_s[i] = d_tw[i];

    for (int p = tid; p < 16 * WW; p += 128) {
        int r = p / WW, w = p % WW;
        const float* px = x_seq + ((((size_t)img * HH + (y0 + r)) * WW) + w) * CIN;
        g_s[w * 17 + r] = (px[0] + px[1] + px[2]) * (1.0f / 3.0f);
    }
    __syncthreads();

    for (int p = tid; p < NF * 16; p += 128) {
        int w = p >> 4, r = p & 15;
        float a = g_s[(w + 1) * 17 + r];
        float b = g_s[(223 - w) * 17 + r];
        s_s[p]  = a + b;
        dd_s[p] = a - b;
    }
    if (tid < 16) { g0_s[tid] = g_s[tid]; g112_s[tid] = g_s[HALF * 17 + tid]; }
    __syncthreads();

    int k = tid;
    if (k >= KW) return;

    float ar[16], ai[16];
    float sgn = (k & 1) ? -1.0f : 1.0f;
    #pragma unroll
    for (int r = 0; r < 16; ++r) {
        ar[r] = g0_s[r] + sgn * g112_s[r];
        ai[r] = 0.0f;
    }

    int idx = k;
    for (int w = 0; w < NF; ++w) {
        float2 t = tw_s[idx];
        const float4* sp = (const float4*)(s_s  + w * 16);
        const float4* dp = (const float4*)(dd_s + w * 16);
        #pragma unroll
        for (int q = 0; q < 4; ++q) {
            float4 sv = sp[q], dv = dp[q];
            ar[q*4+0] = fmaf(sv.x, t.x, ar[q*4+0]);
            ar[q*4+1] = fmaf(sv.y, t.x, ar[q*4+1]);
            ar[q*4+2] = fmaf(sv.z, t.x, ar[q*4+2]);
            ar[q*4+3] = fmaf(sv.w, t.x, ar[q*4+3]);
            ai[q*4+0] = fmaf(dv.x, t.y, ai[q*4+0]);
            ai[q*4+1] = fmaf(dv.y, t.y, ai[q*4+1]);
            ai[q*4+2] = fmaf(dv.z, t.y, ai[q*4+2]);
            ai[q*4+3] = fmaf(dv.w, t.y, ai[q*4+3]);
        }
        idx += k; if (idx >= WW) idx -= WW;
    }

    float4* out = (float4*)(d_rowspec + (size_t)img * MAGN + (size_t)k * HH + y0);
    #pragma unroll
    for (int j = 0; j < 8; ++j)
        out[j] = make_float4(ar[2*j], ai[2*j], ar[2*j+1], ai[2*j+1]);
}

// ============================================================
// K2: column full DFT (folded) + log1p(|.|) + energy.
// ============================================================
__global__ void __launch_bounds__(224) k_coldft() {
    int blk = blockIdx.x;             // img*15 + kg
    int img = blk / 15;
    int k0  = (blk % 15) * 8;
    int nk  = KW - k0; if (nk > 8) nk = 8;

    __shared__ float2 zraw[8 * 225];      // [kk][h], stride 225
    __shared__ float2 zs_s[NF * 8];       // [w][kk]
    __shared__ float2 zd_s[NF * 8];
    __shared__ float2 z0_s[8], z112_s[8];
    __shared__ float2 tw_s[WW];
    __shared__ float  wsum[7];

    int tid = threadIdx.x;
    for (int i = tid; i < WW; i += 224) tw_s[i] = d_tw[i];

    for (int p = tid; p < 8 * HH; p += 224) {
        int kk = p / HH, h = p % HH;
        float2 z = make_float2(0.0f, 0.0f);
        if (kk < nk)
            z = d_rowspec[(size_t)img * MAGN + (size_t)(k0 + kk) * HH + h];
        zraw[kk * 225 + h] = z;
    }
    __syncthreads();

    for (int p = tid; p < NF * 8; p += 224) {
        int kk = p & 7, w = p >> 3;
        float2 a = zraw[kk * 225 + (w + 1)];
        float2 b = zraw[kk * 225 + (223 - w)];
        zs_s[w * 8 + kk] = make_float2(a.x + b.x, a.y + b.y);
        zd_s[w * 8 + kk] = make_float2(a.x - b.x, a.y - b.y);
    }
    if (tid < 8) {
        z0_s[tid]   = zraw[tid * 225];
        z112_s[tid] = zraw[tid * 225 + HALF];
    }
    __syncthreads();

    int m = tid;                           // 0..223
    float ar[8], ai[8];
    float sgn = (m & 1) ? -1.0f : 1.0f;
    #pragma unroll
    for (int kk = 0; kk < 8; ++kk) {
        ar[kk] = z0_s[kk].x + sgn * z112_s[kk].x;
        ai[kk] = z0_s[kk].y + sgn * z112_s[kk].y;
    }

    int idx = m;
    for (int w = 0; w < NF; ++w) {
        float2 t = tw_s[idx];
        const float4* zsp = (const float4*)(zs_s + w * 8);
        const float4* zdp = (const float4*)(zd_s + w * 8);
        #pragma unroll
        for (int q = 0; q < 4; ++q) {
            float4 a = zsp[q], b = zdp[q];
            ar[2*q]   = fmaf(a.x, t.x, fmaf(-b.y, t.y, ar[2*q]));
            ai[2*q]   = fmaf(a.y, t.x, fmaf( b.x, t.y, ai[2*q]));
            ar[2*q+1] = fmaf(a.z, t.x, fmaf(-b.w, t.y, ar[2*q+1]));
            ai[2*q+1] = fmaf(a.w, t.x, fmaf( b.z, t.y, ai[2*q+1]));
        }
        idx += m; if (idx >= WW) idx -= WW;
    }

    float esum = 0.0f;
    float* mrow = d_mag + (size_t)img * MAGN + (size_t)m * KW + k0;
    #pragma unroll
    for (int kk = 0; kk < 8; ++kk) {
        if (kk < nk) {
            float mag = log1pf(sqrtf(fmaf(ar[kk], ar[kk], ai[kk] * ai[kk])));
            mrow[kk] = mag;
            esum += mag;
        }
    }
    #pragma unroll
    for (int o = 16; o; o >>= 1) esum += __shfl_down_sync(0xffffffffu, esum, o);
    if ((tid & 31) == 0) wsum[tid >> 5] = esum;
    __syncthreads();
    if (tid == 0) {
        float tot = 0.0f;
        #pragma unroll
        for (int i = 0; i < 7; ++i) tot += wsum[i];
        atomicAdd(&d_esum, (double)tot);
    }
}

// ============================================================
// K3: fused 3x3 conv (4->32 ch) + LIF scan over T.
//  - double-buffered input tiles; LDG(t+1) issued before FMA(t),
//    STS(t+1) after (software pipeline) -> one barrier/timestep
//  - smem rows padded to 20 floats -> LDS.128 row loads
//  - spike counts in cnt_s[16][32], zeroed once, flushed once
// ============================================================
__global__ void __launch_bounds__(256, 2)
k_convlif(const float* __restrict__ x_seq,
          const float* __restrict__ conv_w,
          const float* __restrict__ conv_b) {
    int b    = blockIdx.y;
    int tile = blockIdx.x;                 // 0..195
    int ty0 = (tile / 14) * 16;
    int tx0 = (tile % 14) * 16;

    int tid = threadIdx.x;
    int c = tid & 31;
    int g = tid >> 5;

    // per-channel weights -> registers
    float wreg[3][3][4];
    #pragma unroll
    for (int ky = 0; ky < 3; ++ky)
        #pragma unroll
        for (int kx = 0; kx < 3; ++kx)
            #pragma unroll
            for (int i = 0; i < 4; ++i)
                wreg[ky][kx][i] = conv_w[(((ky * 3) + kx) * 4 + i) * CH + c];
    float bc = conv_b[c];

    __shared__ float tile_s[2][4][18][20];   // padded rows (LDS.128-aligned)
    __shared__ int   cnt_s[T_STEPS][CH];

    // zero spike counters once
    cnt_s[tid >> 5][(tid & 31)] = 0;                    // rows 0..7
    cnt_s[8 + (tid >> 5)][(tid & 31)] = 0;              // rows 8..15

    float V[2][16];
    #pragma unroll
    for (int r = 0; r < 2; ++r)
        #pragma unroll
        for (int x = 0; x < 16; ++x) V[r][x] = 0.0f;

    const float scale = 113.0f / 224.0f;

    // ---- staging helpers (2 strided items per thread: p = tid, tid+256) ----
    // item 1 only valid when tid < 68 (324 - 256).
    int yy0 = tid / 18,          xx0 = tid % 18;
    int p1  = tid + 256;
    int yy1 = p1 / 18,           xx1 = p1 % 18;
    bool has1 = (tid < 68);

    float st_r[2][3], st_a[2], st_b[2], st_f[2];

    // load phase: gmem -> regs for timestep tt
    auto stage_load = [&](int tt) {
        int img = tt * BATCH + b;
        const float* mbase = d_mag + (size_t)img * MAGN;
        #pragma unroll
        for (int it = 0; it < 2; ++it) {
            int yy = it ? yy1 : yy0;
            int xx = it ? xx1 : xx0;
            if (it && !has1) break;
            int gy = ty0 - 1 + yy, gx = tx0 - 1 + xx;
            float r0 = 0.f, r1 = 0.f, r2 = 0.f, a = 0.f, bb = 0.f, f = 0.f;
            if (gy >= 0 && gy < HH && gx >= 0 && gx < WW) {
                const float* px = x_seq + ((((size_t)img * HH + gy) * WW) + gx) * CIN;
                r0 = px[0]; r1 = px[1]; r2 = px[2];
                float src = fmaf((float)gx + 0.5f, scale, -0.5f);
                src = fminf(fmaxf(src, 0.0f), 112.0f);
                int i0 = (int)src; if (i0 > 111) i0 = 111;
                f = src - (float)i0;
                const float* mrow = mbase + (size_t)gy * KW;
                a  = mrow[i0];
                bb = mrow[i0 + 1];
            }
            st_r[it][0] = r0; st_r[it][1] = r1; st_r[it][2] = r2;
            st_a[it] = a; st_b[it] = bb; st_f[it] = f;
        }
    };
    // store phase: regs -> smem buffer `buf`
    auto stage_store = [&](int buf) {
        #pragma unroll
        for (int it = 0; it < 2; ++it) {
            int yy = it ? yy1 : yy0;
            int xx = it ? xx1 : xx0;
            if (it && !has1) break;
            tile_s[buf][0][yy][xx] = st_r[it][0];
            tile_s[buf][1][yy][xx] = st_r[it][1];
            tile_s[buf][2][yy][xx] = st_r[it][2];
            tile_s[buf][3][yy][xx] = fmaf(st_f[it], st_b[it] - st_a[it], st_a[it]);
        }
    };

    // prologue: stage t=0
    stage_load(0);
    stage_store(0);
    __syncthreads();

    for (int t = 0; t < T_STEPS; ++t) {
        int buf = t & 1;

        // issue next timestep's gmem loads early (latency hidden by FMAs)
        if (t + 1 < T_STEPS) stage_load(t + 1);

        // ---- leak + bias ----
        #pragma unroll
        for (int r = 0; r < 2; ++r)
            #pragma unroll
            for (int x = 0; x < 16; ++x)
                V[r][x] = fmaf(0.9f, V[r][x], bc);

        // ---- conv taps (rows via LDS.128) ----
        const float (*tp)[18][20] = tile_s[buf];
        #pragma unroll
        for (int i = 0; i < 4; ++i) {
            #pragma unroll
            for (int iy = 0; iy < 4; ++iy) {
                const float4* rowp = (const float4*)&tp[i][2 * g + iy][0];
                float v[20];
                #pragma unroll
                for (int q = 0; q < 5; ++q) ((float4*)v)[q] = rowp[q];
                if (iy < 3) {
                    float w0 = wreg[iy][0][i], w1 = wreg[iy][1][i], w2 = wreg[iy][2][i];
                    #pragma unroll
                    for (int x = 0; x < 16; ++x)
                        V[0][x] = fmaf(w0, v[x], fmaf(w1, v[x + 1], fmaf(w2, v[x + 2], V[0][x])));
                }
                if (iy >= 1) {
                    float w0 = wreg[iy - 1][0][i], w1 = wreg[iy - 1][1][i], w2 = wreg[iy - 1][2][i];
                    #pragma unroll
                    for (int x = 0; x < 16; ++x)
                        V[1][x] = fmaf(w0, v[x], fmaf(w1, v[x + 1], fmaf(w2, v[x + 2], V[1][x])));
                }
            }
        }

        // ---- spike + soft reset + count ----
        int cnt = 0;
        #pragma unroll
        for (int r = 0; r < 2; ++r)
            #pragma unroll
            for (int x = 0; x < 16; ++x) {
                if (V[r][x] > 1.0f) { V[r][x] -= 1.0f; ++cnt; }
            }
        atomicAdd(&cnt_s[t][c], cnt);

        // write next tile (stalls on LDG completion only here)
        if (t + 1 < T_STEPS) stage_store((t + 1) & 1);

        __syncthreads();
    }

    // flush spike counts (2 entries per thread)
    {
        int t0 = tid >> 5;
        atomicAdd(&d_counts[(t0 * BATCH + b) * CH + c], cnt_s[t0][c]);
        int t1 = 8 + (tid >> 5);
        atomicAdd(&d_counts[(t1 * BATCH + b) * CH + c], cnt_s[t1][c]);
    }
}

// ============================================================
// K4: head matmul + readout + scalars.
// ============================================================
__global__ void k_final(const float* __restrict__ head_w,
                        const float* __restrict__ head_b,
                        float* __restrict__ out) {
    __shared__ float logits_s[T_STEPS][BATCH][OUT];
    int tid = threadIdx.x;

    if (tid < T_STEPS * BATCH) {
        int t = tid >> 3, b = tid & 7;
        const float inv = 1.0f / (float)(HH * WW);
        float mean[CH];
        #pragma unroll
        for (int c = 0; c < CH; ++c)
            mean[c] = (float)d_counts[(t * BATCH + b) * CH + c] * inv;
        #pragma unroll
        for (int o = 0; o < OUT; ++o) {
            float a = head_b[o];
            #pragma unroll
            for (int c = 0; c < CH; ++c)
                a = fmaf(mean[c], head_w[c * OUT + o], a);
            logits_s[t][b][o] = a;
            out[80 + (t * BATCH + b) * OUT + o] = a;
        }
    }
    __syncthreads();
    if (tid < BATCH * OUT) {
        int b = tid / OUT, o = tid % OUT;
        float s = 0.0f;
        #pragma unroll
        for (int t = 0; t < T_STEPS; ++t) s += logits_s[t][b][o];
        out[tid] = s * (1.0f / (float)T_STEPS);
    }
    if (tid == 0) {
        long long tot = 0;
        for (int i = 0; i < T_STEPS * BATCH * CH; ++i) tot += (long long)d_counts[i];
        out[1360] = (float)((double)tot /
                            ((double)T_STEPS * BATCH * HH * WW * CH));
        out[1361] = (float)(d_esum / ((double)T_STEPS * BATCH * HH * KW));
    }
}

// ============================================================
extern "C" void kernel_launch(void* const* d_in, const int* in_sizes, int n_in,
                              void* d_out, int out_size) {
    const float* x_seq  = (const float*)d_in[0];
    const float* conv_w = (const float*)d_in[1];
    const float* conv_b = (const float*)d_in[2];
    const float* head_w = (const float*)d_in[3];
    const float* head_b = (const float*)d_in[4];
    float* out = (float*)d_out;

    k_init<<<16, 256>>>();
    k_rowdft<<<NIMG * 14, 128>>>(x_seq);
    k_coldft<<<NIMG * 15, 224>>>();
    k_convlif<<<dim3(14 * 14, BATCH), 256>>>(x_seq, conv_w, conv_b);
    k_final<<<1, 256>>>(head_w, head_b, out);
}